// round 15
// baseline (speedup 1.0000x reference)
#include <cuda_runtime.h>
#include <cuda_fp16.h>
#include <cstdint>
#include <math.h>

#define BDIM 4096
#define DDIM 2048
#define KDIM 2048

// ---------------- device scratch ----------------
// g_flags is monotone-correct across replays: zero-initialized at load; a set
// flag only routes extra inputs through the (mathematically general) slow path.
__device__ int      g_flags[2];            // [0] mem0 nonzero, [1] out0 nonzero
__device__ unsigned g_barcnt = 0;          // software grid barrier state
__device__ unsigned g_bargen = 0;
__device__ float  g_preA[BDIM * DDIM];
__device__ float  g_preB[BDIM * DDIM];
__device__ __half g_ax  [BDIM * KDIM];
__device__ __half g_ay  [BDIM * KDIM];     // out0 fp16
__device__ __half g_az  [BDIM * KDIM];     // mem0 fp16
__device__ __half g_au  [BDIM * KDIM];     // sigmoid(preC)*mem0 fp16
__device__ __half g_w0  [DDIM * KDIM];
__device__ __half g_w1  [DDIM * KDIM];
__device__ __half g_w2  [DDIM * KDIM];
__device__ __half g_w3  [DDIM * KDIM];
__device__ __half g_w4  [DDIM * KDIM];
__device__ __half g_w5  [DDIM * KDIM];
__device__ __half g_w6  [DDIM * KDIM];

// split-K tail scratch for the dual GEMM (136 pairs x 256 thr x 64 floats)
#define NFULL 888
#define NPAIR 136
__device__ float g_part [NPAIR * 16384];
__device__ int   g_tflag[NPAIR];           // consume-reset: always 0 between replays

// flat, byte-balanced prep: 5 jobs over one 1-D grid
#define NPREP 5
struct PrepFlat {
    const float4* src[NPREP];
    uint2*        dst[NPREP];
    int           n4[NPREP];
    int           mode[NPREP];   // 0 = conv, 1 = scan -> flags[flagidx]
    int           flagidx[NPREP];
    int           blk0[NPREP + 1];
};

// full slow-path descriptor (one persistent kernel)
struct SlowDesc {
    const float4* csrc[9];
    uint2*        cdst[9];
    int           cn4[9];
    int           cfs[9];
    const __half* A2[3][3];
    const __half* W2[3][3];
    int           pfs2[3][3];
    int           np2[3];
    float*        C2[3];
    const float*  bb0[3];
    const float*  bb1[3];
    const float*  bb2[3];
    int           sfs2[3];
    int           epi2[3];      // 0 = accum into C2, 2 = au = f16(sig(c+b)*mem0)
    const __half* Adec;
    const __half* Wdec;
    const float*  bdec;
    const float*  preA_in;
    const float*  preB_in;
    float*        outp;
    const float*  mem0;
    __half*       aup;
};

__device__ __forceinline__ float sigmoidf_(float v) { return 1.0f / (1.0f + expf(-v)); }

__device__ __forceinline__ uint32_t smem_to_u32(const void* p) {
    uint32_t a;
    asm("{ .reg .u64 t; cvta.to.shared.u64 t, %1; cvt.u32.u64 %0, t; }" : "=r"(a) : "l"(p));
    return a;
}

__device__ __forceinline__ void cp16(uint32_t dst, const void* src) {
    asm volatile("cp.async.cg.shared.global [%0], [%1], 16;" :: "r"(dst), "l"(src) : "memory");
}
#define CP_COMMIT() asm volatile("cp.async.commit_group;" ::: "memory")

__device__ __forceinline__ void ldm_x4(uint32_t& r0, uint32_t& r1, uint32_t& r2, uint32_t& r3,
                                       uint32_t addr) {
    asm volatile("ldmatrix.sync.aligned.m8n8.x4.shared.b16 {%0,%1,%2,%3}, [%4];"
                 : "=r"(r0), "=r"(r1), "=r"(r2), "=r"(r3) : "r"(addr));
}

__device__ __forceinline__ void mma_fp16(float* c, const uint32_t* a, const uint32_t* b) {
    asm volatile("mma.sync.aligned.m16n8k16.row.col.f32.f16.f16.f32 "
                 "{%0,%1,%2,%3}, {%4,%5,%6,%7}, {%8,%9}, {%0,%1,%2,%3};"
                 : "+f"(c[0]), "+f"(c[1]), "+f"(c[2]), "+f"(c[3])
                 : "r"(a[0]), "r"(a[1]), "r"(a[2]), "r"(a[3]), "r"(b[0]), "r"(b[1]));
}

__device__ __forceinline__ bool flag_ok(int fs) {
    if (fs == 0) return true;
    if (fs == 4) return (g_flags[0] | g_flags[1]) != 0;
    if (fs == 5) return (g_flags[1] != 0) && (g_flags[0] == 0);
    if ((fs & 1) && g_flags[0] == 0) return false;
    if ((fs & 2) && g_flags[1] == 0) return false;
    return true;
}

// replay-safe software grid barrier (all CTAs resident: grid=296, 2 CTAs/SM)
__device__ __forceinline__ void grid_barrier(unsigned nblocks) {
    __syncthreads();
    if (threadIdx.x == 0) {
        volatile unsigned* vg = &g_bargen;
        unsigned gen = *vg;
        __threadfence();
        if (atomicAdd(&g_barcnt, 1u) == nblocks - 1u) {
            g_barcnt = 0;
            __threadfence();
            atomicAdd(&g_bargen, 1u);
        } else {
            while (*vg == gen) { }
        }
        __threadfence();
    }
    __syncthreads();
}

// ---------------- flat, byte-balanced prep (32B reads / 16B writes) ----------
__global__ void prep_flat_kernel(PrepFlat pf) {
    int z = 0;
    #pragma unroll
    for (int k = 1; k < NPREP; k++)
        if ((int)blockIdx.x >= pf.blk0[k]) z = k;
    const int lb = (int)blockIdx.x - pf.blk0[z];
    const int nb = pf.blk0[z + 1] - pf.blk0[z];
    const int n8 = pf.n4[z] >> 1;
    const float4* __restrict__ src = pf.src[z];

    if (pf.mode[z] == 1) {
        bool nz = false;
        for (int i = lb * 256 + threadIdx.x; i < n8; i += nb * 256) {
            float4 v0 = src[2 * i];
            float4 v1 = src[2 * i + 1];
            nz |= (v0.x != 0.0f) | (v0.y != 0.0f) | (v0.z != 0.0f) | (v0.w != 0.0f);
            nz |= (v1.x != 0.0f) | (v1.y != 0.0f) | (v1.z != 0.0f) | (v1.w != 0.0f);
        }
        if (nz) atomicOr(&g_flags[pf.flagidx[z]], 1);
        return;
    }
    uint4* __restrict__ dst = (uint4*)pf.dst[z];
    for (int i = lb * 256 + threadIdx.x; i < n8; i += nb * 256) {
        float4 v0 = src[2 * i];
        float4 v1 = src[2 * i + 1];
        __half2 h0 = __floats2half2_rn(v0.x, v0.y);
        __half2 h1 = __floats2half2_rn(v0.z, v0.w);
        __half2 h2 = __floats2half2_rn(v1.x, v1.y);
        __half2 h3 = __floats2half2_rn(v1.z, v1.w);
        uint4 o;
        o.x = *(uint32_t*)&h0;
        o.y = *(uint32_t*)&h1;
        o.z = *(uint32_t*)&h2;
        o.w = *(uint32_t*)&h3;
        dst[i] = o;
    }
}

// ================= shared tiling constants =================
#define BK 64
#define CHUNKS (KDIM / BK)
#define STRB 144
#define NSTAGE 3

#define CTAM 128
#define CTAN 128
#define A_BYTES (CTAM * STRB)
#define B_BYTES (CTAN * STRB)
#define STAGE_BYTES (A_BYTES + B_BYTES)
#define GEMM_SMEM (NSTAGE * STAGE_BYTES)    // 110592

// ---------------- tile core (slow path) ----------------
__device__ void gemm_tile(uint32_t sb0, int tid, int bm, int bn,
                          int npairs, const __half* const* Ap,
                          const __half* const* Wp, const int* pfs,
                          float c[4][4][4])
{
    const int lane = tid & 31;
    const int wid = tid >> 5;
    const int wm = wid & 1;
    const int wn = wid >> 1;
    const uint32_t a_row = (uint32_t)(wm * 64 + (lane & 15));
    const uint32_t a_kb  = (uint32_t)((lane >> 4) * 16);
    const uint32_t b_row = (uint32_t)(wn * 32 + (lane & 7) + ((lane & 16) ? 8 : 0));
    const uint32_t b_kb  = (uint32_t)((lane & 8) ? 16 : 0);

    for (int p = 0; p < npairs; p++) {
        if (!flag_ok(pfs[p])) continue;
        const __half* __restrict__ A = Ap[p];
        const __half* __restrict__ W = Wp[p];

        auto load_chunk = [&](int stage, int kt) {
            const uint32_t sb = sb0 + (uint32_t)stage * STAGE_BYTES;
            #pragma unroll
            for (int i = 0; i < 4; i++) {
                int gr = tid + i * 256;
                int row = gr >> 3, c8 = gr & 7;
                cp16(sb + (uint32_t)(row * STRB + c8 * 16),
                     A + (size_t)(bm + row) * KDIM + kt + c8 * 8);
            }
            #pragma unroll
            for (int i = 0; i < 4; i++) {
                int gr = tid + i * 256;
                int row = gr >> 3, c8 = gr & 7;
                cp16(sb + (uint32_t)(A_BYTES + row * STRB + c8 * 16),
                     W + (size_t)(bn + row) * KDIM + kt + c8 * 8);
            }
            CP_COMMIT();
        };

        load_chunk(0, 0);
        load_chunk(1, BK);

        int stage = 0;
        for (int ch = 0; ch < CHUNKS; ch++) {
            if (ch + 2 < CHUNKS) {
                int ns = stage + 2; if (ns >= NSTAGE) ns -= NSTAGE;
                load_chunk(ns, (ch + 2) * BK);
                asm volatile("cp.async.wait_group 2;" ::: "memory");
            } else if (ch + 1 < CHUNKS) {
                asm volatile("cp.async.wait_group 1;" ::: "memory");
            } else {
                asm volatile("cp.async.wait_group 0;" ::: "memory");
            }
            __syncthreads();

            const uint32_t As = sb0 + (uint32_t)stage * STAGE_BYTES;
            const uint32_t Bs = As + A_BYTES;

            #pragma unroll
            for (int s = 0; s < 4; s++) {
                const uint32_t kb = (uint32_t)(s * 32);
                uint32_t a[4][4];
                #pragma unroll
                for (int mf = 0; mf < 4; mf++)
                    ldm_x4(a[mf][0], a[mf][1], a[mf][2], a[mf][3],
                           As + (a_row + mf * 16) * STRB + kb + a_kb);
                uint32_t b[4][2];
                #pragma unroll
                for (int nh = 0; nh < 2; nh++) {
                    uint32_t r0, r1, r2, r3;
                    ldm_x4(r0, r1, r2, r3, Bs + (b_row + nh * 16) * STRB + kb + b_kb);
                    b[2 * nh][0] = r0;      b[2 * nh][1] = r1;
                    b[2 * nh + 1][0] = r2;  b[2 * nh + 1][1] = r3;
                }
                #pragma unroll
                for (int mf = 0; mf < 4; mf++)
                    #pragma unroll
                    for (int nf = 0; nf < 4; nf++)
                        mma_fp16(c[mf][nf], a[mf], b[nf]);
            }
            __syncthreads();
            if (++stage >= NSTAGE) stage = 0;
        }
    }
}

// ---------------- persistent slow-path mega kernel ----------------
__global__ __launch_bounds__(256, 2)
void slow_mega(SlowDesc sd)
{
    if ((g_flags[0] | g_flags[1]) == 0) return;

    extern __shared__ char smem[];
    const uint32_t sb0 = smem_to_u32(smem);
    const int tid = threadIdx.x;
    const unsigned nb = gridDim.x;

    for (int z = 0; z < 9; z++) {
        if (!flag_ok(sd.cfs[z])) continue;
        const float4* __restrict__ src = sd.csrc[z];
        uint2* __restrict__ dst = sd.cdst[z];
        const int n4 = sd.cn4[z];
        for (int i = blockIdx.x * 256 + tid; i < n4; i += nb * 256) {
            float4 v = src[i];
            __half2 h0 = __floats2half2_rn(v.x, v.y);
            __half2 h1 = __floats2half2_rn(v.z, v.w);
            uint2 o;
            o.x = *(uint32_t*)&h0;
            o.y = *(uint32_t*)&h1;
            dst[i] = o;
        }
    }
    grid_barrier(nb);

    const int lane = tid & 31;
    const int wid = tid >> 5;
    const int g = lane >> 2;
    const int t = lane & 3;
    const int wm = wid & 1;
    const int wn = wid >> 1;

    for (int ti = blockIdx.x; ti < 3 * 512; ti += (int)nb) {
        const int z = ti >> 9;
        const int tt = ti & 511;
        if (!flag_ok(sd.sfs2[z])) continue;
        const int bn = (tt & 15) * CTAN;
        const int bm = (tt >> 4) * CTAM;

        float c[4][4][4];
        #pragma unroll
        for (int i = 0; i < 4; i++)
            #pragma unroll
            for (int j = 0; j < 4; j++)
                #pragma unroll
                for (int q = 0; q < 4; q++) c[i][j][q] = 0.0f;

        gemm_tile(sb0, tid, bm, bn, sd.np2[z], sd.A2[z], sd.W2[z], sd.pfs2[z], c);

        if (sd.epi2[z] == 2) {
            const float* __restrict__ m0p = sd.mem0;
            __half* __restrict__ aup = sd.aup;
            const float* b0 = sd.bb0[z];
            const float* b1 = sd.bb1[z];
            const float* b2 = sd.bb2[z];
            #pragma unroll
            for (int nf = 0; nf < 4; nf++) {
                const int col = bn + wn * 32 + nf * 8 + 2 * t;
                float bs0 = b0[col] + b1[col] + b2[col];
                float bs1 = b0[col + 1] + b1[col + 1] + b2[col + 1];
                #pragma unroll
                for (int mf = 0; mf < 4; mf++) {
                    const int r = bm + wm * 64 + mf * 16 + g;
                    float2 v0 = make_float2(c[mf][nf][0] + bs0, c[mf][nf][1] + bs1);
                    float2 v1 = make_float2(c[mf][nf][2] + bs0, c[mf][nf][3] + bs1);
                    float2 m0 = *(const float2*)(m0p + (size_t)r * DDIM + col);
                    float2 m1 = *(const float2*)(m0p + (size_t)(r + 8) * DDIM + col);
                    __half2 h0 = __floats2half2_rn(sigmoidf_(v0.x) * m0.x,
                                                   sigmoidf_(v0.y) * m0.y);
                    __half2 h1 = __floats2half2_rn(sigmoidf_(v1.x) * m1.x,
                                                   sigmoidf_(v1.y) * m1.y);
                    *(__half2*)(aup + (size_t)r * KDIM + col) = h0;
                    *(__half2*)(aup + (size_t)(r + 8) * KDIM + col) = h1;
                }
            }
        } else {
            float* __restrict__ C = sd.C2[z];
            #pragma unroll
            for (int nf = 0; nf < 4; nf++) {
                const int col = bn + wn * 32 + nf * 8 + 2 * t;
                #pragma unroll
                for (int mf = 0; mf < 4; mf++) {
                    const int r = bm + wm * 64 + mf * 16 + g;
                    float2* p0 = (float2*)(C + (size_t)r * DDIM + col);
                    float2* p1 = (float2*)(C + (size_t)(r + 8) * DDIM + col);
                    float2 o0 = *p0, o1 = *p1;
                    o0.x += c[mf][nf][0]; o0.y += c[mf][nf][1];
                    o1.x += c[mf][nf][2]; o1.y += c[mf][nf][3];
                    *p0 = o0;
                    *p1 = o1;
                }
            }
        }
    }
    grid_barrier(nb);

    for (int ti = blockIdx.x; ti < 2 * 512; ti += (int)nb) {
        const int z = ti >> 9;
        const int tt = ti & 511;
        const int bn = (tt & 15) * CTAN;
        const int bm = (tt >> 4) * CTAM;

        if (z == 0) {
            if (g_flags[0] == 0) continue;
            float c[4][4][4];
            #pragma unroll
            for (int i = 0; i < 4; i++)
                #pragma unroll
                for (int j = 0; j < 4; j++)
                    #pragma unroll
                    for (int q = 0; q < 4; q++) c[i][j][q] = 0.0f;
            const __half* Ap[1] = { sd.Adec };
            const __half* Wp[1] = { sd.Wdec };
            const int pf[1] = { 0 };
            gemm_tile(sb0, tid, bm, bn, 1, Ap, Wp, pf, c);

            #pragma unroll
            for (int nf = 0; nf < 4; nf++) {
                const int col = bn + wn * 32 + nf * 8 + 2 * t;
                const float d0 = sd.bdec[col], d1 = sd.bdec[col + 1];
                #pragma unroll
                for (int mf = 0; mf < 4; mf++) {
                    const int r = bm + wm * 64 + mf * 16 + g;
                    float2 pa0 = *(const float2*)(sd.preA_in + (size_t)r * DDIM + col);
                    float2 pa1 = *(const float2*)(sd.preA_in + (size_t)(r + 8) * DDIM + col);
                    float2 pb0 = *(const float2*)(sd.preB_in + (size_t)r * DDIM + col);
                    float2 pb1 = *(const float2*)(sd.preB_in + (size_t)(r + 8) * DDIM + col);
                    float2 o0, o1;
                    o0.x = c[mf][nf][0] + d0 + sigmoidf_(pa0.x) * sigmoidf_(pb0.x);
                    o0.y = c[mf][nf][1] + d1 + sigmoidf_(pa0.y) * sigmoidf_(pb0.y);
                    o1.x = c[mf][nf][2] + d0 + sigmoidf_(pa1.x) * sigmoidf_(pb1.x);
                    o1.y = c[mf][nf][3] + d1 + sigmoidf_(pa1.y) * sigmoidf_(pb1.y);
                    *(float2*)(sd.outp + (size_t)r * DDIM + col) = o0;
                    *(float2*)(sd.outp + (size_t)(r + 8) * DDIM + col) = o1;
                }
            }
        } else {
            if (!(g_flags[1] != 0 && g_flags[0] == 0)) continue;
            #pragma unroll
            for (int nf = 0; nf < 4; nf++) {
                const int col = bn + wn * 32 + nf * 8 + 2 * t;
                const float d0 = sd.bdec[col], d1 = sd.bdec[col + 1];
                #pragma unroll
                for (int mf = 0; mf < 4; mf++) {
                    const int r = bm + wm * 64 + mf * 16 + g;
                    float2 pa0 = *(const float2*)(sd.preA_in + (size_t)r * DDIM + col);
                    float2 pa1 = *(const float2*)(sd.preA_in + (size_t)(r + 8) * DDIM + col);
                    float2 pb0 = *(const float2*)(sd.preB_in + (size_t)r * DDIM + col);
                    float2 pb1 = *(const float2*)(sd.preB_in + (size_t)(r + 8) * DDIM + col);
                    float2 o0, o1;
                    o0.x = d0 + sigmoidf_(pa0.x) * sigmoidf_(pb0.x);
                    o0.y = d1 + sigmoidf_(pa0.y) * sigmoidf_(pb0.y);
                    o1.x = d0 + sigmoidf_(pa1.x) * sigmoidf_(pb1.x);
                    o1.y = d1 + sigmoidf_(pa1.y) * sigmoidf_(pb1.y);
                    *(float2*)(sd.outp + (size_t)r * DDIM + col) = o0;
                    *(float2*)(sd.outp + (size_t)(r + 8) * DDIM + col) = o1;
                }
            }
        }
    }
}

// ---------------- dual-output GEMM (fast path) with split-K tail ----------
#define DCTAM 128
#define DCTAN 64
#define D_A_BYTES (DCTAM * STRB)                 // 18432
#define D_W_BYTES (DCTAN * STRB)                 // 9216
#define D_STAGE (D_A_BYTES + 2 * D_W_BYTES)      // 36864
#define DGEMM_SMEM (NSTAGE * D_STAGE)            // 110592

__global__ __launch_bounds__(256, 2)
void gemm_dual(const __half* __restrict__ A,
               const __half* __restrict__ W0, const __half* __restrict__ W1,
               float* __restrict__ preA, float* __restrict__ preB,
               const float* __restrict__ bA0, const float* __restrict__ bA1,
               const float* __restrict__ bB0, const float* __restrict__ bB1,
               const float* __restrict__ bB2,
               float* __restrict__ outp, const float* __restrict__ bdec)
{
    extern __shared__ char smem[];
    const uint32_t sb0 = smem_to_u32(smem);

    const int tid = threadIdx.x;
    const int wid = tid >> 5;
    const int lane = tid & 31;
    const int g = lane >> 2;
    const int t = lane & 3;
    const int wm = wid & 1;
    const int wn = wid >> 1;

    // ---- tile / split-K assignment ----
    const int bid = (int)blockIdx.x;
    int ti, k0, nch, pairid = -1;
    bool producer = false;
    if (bid < NFULL) {
        ti = bid; k0 = 0; nch = CHUNKS;
    } else {
        const int q = bid - NFULL;
        pairid = q >> 1;
        producer = (q & 1) == 0;      // lower blockIdx -> scheduled first
        ti = NFULL + pairid;
        nch = CHUNKS / 2;
        k0 = producer ? (CHUNKS / 2) * BK : 0;
    }
    const int bm = (ti >> 5) * DCTAM;
    const int bn = (ti & 31) * DCTAN;

    float cA[4][2][4], cB[4][2][4];
    #pragma unroll
    for (int i = 0; i < 4; i++)
        #pragma unroll
        for (int j = 0; j < 2; j++)
            #pragma unroll
            for (int q = 0; q < 4; q++) { cA[i][j][q] = 0.0f; cB[i][j][q] = 0.0f; }

    const uint32_t a_row = (uint32_t)(wm * 64 + (lane & 15));
    const uint32_t a_kb  = (uint32_t)((lane >> 4) * 16);
    const uint32_t b_row = (uint32_t)(wn * 16 + (lane & 7) + ((lane & 16) ? 8 : 0));
    const uint32_t b_kb  = (uint32_t)((lane & 8) ? 16 : 0);

    auto load_chunk = [&](int stage, int kt) {
        const uint32_t sb = sb0 + (uint32_t)stage * D_STAGE;
        #pragma unroll
        for (int i = 0; i < 4; i++) {
            int gr = tid + i * 256;
            int row = gr >> 3, c8 = gr & 7;
            cp16(sb + (uint32_t)(row * STRB + c8 * 16),
                 A + (size_t)(bm + row) * KDIM + kt + c8 * 8);
        }
        #pragma unroll
        for (int i = 0; i < 2; i++) {
            int gr = tid + i * 256;
            int row = gr >> 3, c8 = gr & 7;
            cp16(sb + (uint32_t)(D_A_BYTES + row * STRB + c8 * 16),
                 W0 + (size_t)(bn + row) * KDIM + kt + c8 * 8);
        }
        #pragma unroll
        for (int i = 0; i < 2; i++) {
            int gr = tid + i * 256;
            int row = gr >> 3, c8 = gr & 7;
            cp16(sb + (uint32_t)(D_A_BYTES + D_W_BYTES + row * STRB + c8 * 16),
                 W1 + (size_t)(bn + row) * KDIM + kt + c8 * 8);
        }
        CP_COMMIT();
    };

    load_chunk(0, k0);
    load_chunk(1, k0 + BK);

    int stage = 0;
    for (int ch = 0; ch < nch; ch++) {
        if (ch + 2 < nch) {
            int ns = stage + 2; if (ns >= NSTAGE) ns -= NSTAGE;
            load_chunk(ns, k0 + (ch + 2) * BK);
            asm volatile("cp.async.wait_group 2;" ::: "memory");
        } else if (ch + 1 < nch) {
            asm volatile("cp.async.wait_group 1;" ::: "memory");
        } else {
            asm volatile("cp.async.wait_group 0;" ::: "memory");
        }
        __syncthreads();

        const uint32_t As  = sb0 + (uint32_t)stage * D_STAGE;
        const uint32_t Bs0 = As + D_A_BYTES;
        const uint32_t Bs1 = Bs0 + D_W_BYTES;

        #pragma unroll
        for (int s = 0; s < 4; s++) {
            const uint32_t kb = (uint32_t)(s * 32);
            uint32_t a[4][4];
            #pragma unroll
            for (int mf = 0; mf < 4; mf++)
                ldm_x4(a[mf][0], a[mf][1], a[mf][2], a[mf][3],
                       As + (a_row + mf * 16) * STRB + kb + a_kb);
            uint32_t b0[2][2], b1[2][2];
            {
                uint32_t r0, r1, r2, r3;
                ldm_x4(r0, r1, r2, r3, Bs0 + b_row * STRB + kb + b_kb);
                b0[0][0] = r0; b0[0][1] = r1; b0[1][0] = r2; b0[1][1] = r3;
                ldm_x4(r0, r1, r2, r3, Bs1 + b_row * STRB + kb + b_kb);
                b1[0][0] = r0; b1[0][1] = r1; b1[1][0] = r2; b1[1][1] = r3;
            }
            #pragma unroll
            for (int mf = 0; mf < 4; mf++)
                #pragma unroll
                for (int nf = 0; nf < 2; nf++) {
                    mma_fp16(cA[mf][nf], a[mf], b0[nf]);
                    mma_fp16(cB[mf][nf], a[mf], b1[nf]);
                }
        }
        __syncthreads();
        if (++stage >= NSTAGE) stage = 0;
    }

    // ---- split-K handshake ----
    if (producer) {
        float* dst = g_part + (size_t)pairid * 16384 + tid * 64;
        #pragma unroll
        for (int mf = 0; mf < 4; mf++)
            #pragma unroll
            for (int nf = 0; nf < 2; nf++)
                #pragma unroll
                for (int q = 0; q < 4; q++) {
                    dst[mf * 8 + nf * 4 + q] = cA[mf][nf][q];
                    dst[32 + mf * 8 + nf * 4 + q] = cB[mf][nf][q];
                }
        __threadfence();
        __syncthreads();
        if (tid == 0) atomicExch(&g_tflag[pairid], 1);
        return;
    }
    if (pairid >= 0) {
        if (tid == 0) {
            while (atomicCAS(&g_tflag[pairid], 1, 0) != 1) { }
            __threadfence();
        }
        __syncthreads();
        const float* srcp = g_part + (size_t)pairid * 16384 + tid * 64;
        #pragma unroll
        for (int mf = 0; mf < 4; mf++)
            #pragma unroll
            for (int nf = 0; nf < 2; nf++)
                #pragma unroll
                for (int q = 0; q < 4; q++) {
                    cA[mf][nf][q] += srcp[mf * 8 + nf * 4 + q];
                    cB[mf][nf][q] += srcp[32 + mf * 8 + nf * 4 + q];
                }
    }

    // ---- fused epilogue ----
    const bool slow = (g_flags[0] | g_flags[1]) != 0;
    #pragma unroll
    for (int nf = 0; nf < 2; nf++) {
        const int col = bn + wn * 16 + nf * 8 + 2 * t;
        const float bsA0 = bA0[col] + bA1[col];
        const float bsA1 = bA0[col + 1] + bA1[col + 1];
        const float bsB0 = bB0[col] + bB1[col] + bB2[col];
        const float bsB1 = bB0[col + 1] + bB1[col + 1] + bB2[col + 1];
        const float d0 = bdec[col], d1 = bdec[col + 1];
        #pragma unroll
        for (int mf = 0; mf < 4; mf++) {
            const int r = bm + wm * 64 + mf * 16 + g;
            float2 va0 = make_float2(cA[mf][nf][0] + bsA0, cA[mf][nf][1] + bsA1);
            float2 va1 = make_float2(cA[mf][nf][2] + bsA0, cA[mf][nf][3] + bsA1);
            float2 vb0 = make_float2(cB[mf][nf][0] + bsB0, cB[mf][nf][1] + bsB1);
            float2 vb1 = make_float2(cB[mf][nf][2] + bsB0, cB[mf][nf][3] + bsB1);
            if (slow) {
                *(float2*)(preA + (size_t)r * DDIM + col) = va0;
                *(float2*)(preA + (size_t)(r + 8) * DDIM + col) = va1;
                *(float2*)(preB + (size_t)r * DDIM + col) = vb0;
                *(float2*)(preB + (size_t)(r + 8) * DDIM + col) = vb1;
            } else {
                float2 o0, o1;
                o0.x = d0 + sigmoidf_(va0.x) * sigmoidf_(vb0.x);
                o0.y = d1 + sigmoidf_(va0.y) * sigmoidf_(vb0.y);
                o1.x = d0 + sigmoidf_(va1.x) * sigmoidf_(vb1.x);
                o1.y = d1 + sigmoidf_(va1.y) * sigmoidf_(vb1.y);
                *(float2*)(outp + (size_t)r * DDIM + col) = o0;
                *(float2*)(outp + (size_t)(r + 8) * DDIM + col) = o1;
            }
        }
    }
}

// ---------------- host orchestration ----------------
extern "C" void kernel_launch(void* const* d_in, const int* in_sizes, int n_in,
                              void* d_out, int out_size) {
    const float* x              = (const float*)d_in[0];
    const float* out0           = (const float*)d_in[1];
    const float* mem0           = (const float*)d_in[2];
    const float* w_inpgate      = (const float*)d_in[3];
    const float* b_inpgate      = (const float*)d_in[4];
    const float* w_rec_inpgate  = (const float*)d_in[5];
    const float* b_rec_inpgate  = (const float*)d_in[6];
    const float* w_mem_inpgate  = (const float*)d_in[7];
    const float* b_mem_inpgate  = (const float*)d_in[8];
    const float* w_inp          = (const float*)d_in[9];
    const float* b_inp          = (const float*)d_in[10];
    const float* w_rec_inp      = (const float*)d_in[11];
    const float* b_rec_inp      = (const float*)d_in[12];
    const float* w_readgate     = (const float*)d_in[13];
    const float* b_readgate     = (const float*)d_in[14];
    const float* w_rec_readgate = (const float*)d_in[15];
    const float* b_rec_readgate = (const float*)d_in[16];
    const float* w_mem_readgate = (const float*)d_in[17];
    const float* b_mem_readgate = (const float*)d_in[18];
    const float* w_decoder      = (const float*)d_in[19];
    const float* b_decoder      = (const float*)d_in[20];
    float* out = (float*)d_out;

    void *pA, *pB, *pax, *pay, *paz, *pau;
    void *pw0, *pw1, *pw2, *pw3, *pw4, *pw5, *pw6;
    cudaGetSymbolAddress(&pA, g_preA); cudaGetSymbolAddress(&pB, g_preB);
    cudaGetSymbolAddress(&pax, g_ax);  cudaGetSymbolAddress(&pay, g_ay);
    cudaGetSymbolAddress(&paz, g_az);  cudaGetSymbolAddress(&pau, g_au);
    cudaGetSymbolAddress(&pw0, g_w0);  cudaGetSymbolAddress(&pw1, g_w1);
    cudaGetSymbolAddress(&pw2, g_w2);  cudaGetSymbolAddress(&pw3, g_w3);
    cudaGetSymbolAddress(&pw4, g_w4);  cudaGetSymbolAddress(&pw5, g_w5);
    cudaGetSymbolAddress(&pw6, g_w6);
    float* preA = (float*)pA;  float* preB = (float*)pB;
    __half* ax = (__half*)pax; __half* ay = (__half*)pay;
    __half* az = (__half*)paz; __half* au = (__half*)pau;
    __half* w0h = (__half*)pw0; __half* w1h = (__half*)pw1; __half* w2h = (__half*)pw2;
    __half* w3h = (__half*)pw3; __half* w4h = (__half*)pw4; __half* w5h = (__half*)pw5;
    __half* w6h = (__half*)pw6;

    cudaFuncSetAttribute(slow_mega, cudaFuncAttributeMaxDynamicSharedMemorySize, GEMM_SMEM);
    cudaFuncSetAttribute(gemm_dual, cudaFuncAttributeMaxDynamicSharedMemorySize, DGEMM_SMEM);

    const int nA4 = (BDIM * KDIM) / 4;
    const int nW4 = (DDIM * KDIM) / 4;

    // L1: flat, byte-balanced ungated prep
    {
        PrepFlat pf = {};
        pf.src[0] = (const float4*)x;         pf.dst[0] = (uint2*)ax;  pf.n4[0] = nA4; pf.mode[0] = 0;
        pf.src[1] = (const float4*)mem0;      pf.n4[1] = nA4; pf.mode[1] = 1; pf.flagidx[1] = 0;
        pf.src[2] = (const float4*)out0;      pf.n4[2] = nA4; pf.mode[2] = 1; pf.flagidx[2] = 1;
        pf.src[3] = (const float4*)w_inp;     pf.dst[3] = (uint2*)w0h; pf.n4[3] = nW4; pf.mode[3] = 0;
        pf.src[4] = (const float4*)w_inpgate; pf.dst[4] = (uint2*)w1h; pf.n4[4] = nW4; pf.mode[4] = 0;
        pf.blk0[0] = 0;
        pf.blk0[1] = 615;
        pf.blk0[2] = 1025;
        pf.blk0[3] = 1435;
        pf.blk0[4] = 1742;
        pf.blk0[5] = 2048;
        prep_flat_kernel<<<2048, 256>>>(pf);
    }

    // L2: dual GEMM with split-K tail (888 full tiles + 136 CTA pairs)
    gemm_dual<<<NFULL + 2 * NPAIR, 256, DGEMM_SMEM>>>(ax, w0h, w1h, preA, preB,
                                                      b_inp, b_rec_inp,
                                                      b_inpgate, b_mem_inpgate, b_rec_inpgate,
                                                      out, b_decoder);

    // L3: persistent slow-path mega kernel (single gated launch)
    {
        SlowDesc sd = {};
        sd.csrc[0] = (const float4*)out0;            sd.cdst[0] = (uint2*)ay;  sd.cn4[0] = nA4; sd.cfs[0] = 2;
        sd.csrc[1] = (const float4*)mem0;            sd.cdst[1] = (uint2*)az;  sd.cn4[1] = nA4; sd.cfs[1] = 1;
        sd.csrc[2] = (const float4*)w_readgate;      sd.cdst[2] = (uint2*)w2h; sd.cn4[2] = nW4; sd.cfs[2] = 1;
        sd.csrc[3] = (const float4*)w_rec_inp;       sd.cdst[3] = (uint2*)w3h; sd.cn4[3] = nW4; sd.cfs[3] = 2;
        sd.csrc[4] = (const float4*)w_rec_inpgate;   sd.cdst[4] = (uint2*)w4h; sd.cn4[4] = nW4; sd.cfs[4] = 2;
        sd.csrc[5] = (const float4*)w_rec_readgate;  sd.cdst[5] = (uint2*)w5h; sd.cn4[5] = nW4; sd.cfs[5] = 3;
        sd.csrc[6] = (const float4*)w_mem_inpgate;   sd.cdst[6] = (uint2*)w0h; sd.cn4[6] = nW4; sd.cfs[6] = 1;
        sd.csrc[7] = (const float4*)w_mem_readgate;  sd.cdst[7] = (uint2*)w1h; sd.cn4[7] = nW4; sd.cfs[7] = 1;
        sd.csrc[8] = (const float4*)w_decoder;       sd.cdst[8] = (uint2*)w6h; sd.cn4[8] = nW4; sd.cfs[8] = 1;
        sd.sfs2[0] = 1; sd.np2[0] = 3; sd.epi2[0] = 2;
        sd.A2[0][0] = ax; sd.W2[0][0] = w2h; sd.pfs2[0][0] = 1;
        sd.A2[0][1] = ay; sd.W2[0][1] = w5h; sd.pfs2[0][1] = 3;
        sd.A2[0][2] = az; sd.W2[0][2] = w1h; sd.pfs2[0][2] = 1;
        sd.bb0[0] = b_readgate; sd.bb1[0] = b_mem_readgate; sd.bb2[0] = b_rec_readgate;
        sd.sfs2[1] = 2; sd.np2[1] = 1; sd.epi2[1] = 0;
        sd.A2[1][0] = ay; sd.W2[1][0] = w3h; sd.pfs2[1][0] = 2;
        sd.C2[1] = preA;
        sd.sfs2[2] = 4; sd.np2[2] = 2; sd.epi2[2] = 0;
        sd.A2[2][0] = ay; sd.W2[2][0] = w4h; sd.pfs2[2][0] = 2;
        sd.A2[2][1] = az; sd.W2[2][1] = w0h; sd.pfs2[2][1] = 1;
        sd.C2[2] = preB;
        sd.Adec = au; sd.Wdec = w6h;
        sd.bdec = b_decoder;
        sd.preA_in = preA; sd.preB_in = preB; sd.outp = out;
        sd.mem0 = mem0; sd.aup = au;
        slow_mega<<<296, 256, GEMM_SMEM>>>(sd);
    }
}

// round 16
// speedup vs baseline: 1.1864x; 1.1864x over previous
#include <cuda_runtime.h>
#include <cuda_fp16.h>
#include <cstdint>
#include <math.h>

#define BDIM 4096
#define DDIM 2048
#define KDIM 2048

// ---------------- device scratch ----------------
// g_flags is monotone-correct across replays: zero-initialized at load; a set
// flag only routes extra inputs through the (mathematically general) slow path.
__device__ int      g_flags[2];            // [0] mem0 nonzero, [1] out0 nonzero
__device__ unsigned g_barcnt = 0;          // software grid barrier state
__device__ unsigned g_bargen = 0;
__device__ float  g_preA[BDIM * DDIM];
__device__ float  g_preB[BDIM * DDIM];
__device__ __half g_ax  [BDIM * KDIM];
__device__ __half g_ay  [BDIM * KDIM];     // out0 fp16
__device__ __half g_az  [BDIM * KDIM];     // mem0 fp16
__device__ __half g_au  [BDIM * KDIM];     // sigmoid(preC)*mem0 fp16
__device__ __half g_w0  [DDIM * KDIM];
__device__ __half g_w1  [DDIM * KDIM];
__device__ __half g_w2  [DDIM * KDIM];
__device__ __half g_w3  [DDIM * KDIM];
__device__ __half g_w4  [DDIM * KDIM];
__device__ __half g_w5  [DDIM * KDIM];
__device__ __half g_w6  [DDIM * KDIM];

// flat, byte-balanced prep: 5 jobs over one 1-D grid
#define NPREP 5
struct PrepFlat {
    const float4* src[NPREP];
    uint2*        dst[NPREP];
    int           n4[NPREP];
    int           mode[NPREP];   // 0 = conv, 1 = scan -> flags[flagidx]
    int           flagidx[NPREP];
    int           blk0[NPREP + 1];
};

// full slow-path descriptor (one persistent kernel)
struct SlowDesc {
    const float4* csrc[9];
    uint2*        cdst[9];
    int           cn4[9];
    int           cfs[9];
    const __half* A2[3][3];
    const __half* W2[3][3];
    int           pfs2[3][3];
    int           np2[3];
    float*        C2[3];
    const float*  bb0[3];
    const float*  bb1[3];
    const float*  bb2[3];
    int           sfs2[3];
    int           epi2[3];      // 0 = accum into C2, 2 = au = f16(sig(c+b)*mem0)
    const __half* Adec;
    const __half* Wdec;
    const float*  bdec;
    const float*  preA_in;
    const float*  preB_in;
    float*        outp;
    const float*  mem0;
    __half*       aup;
};

__device__ __forceinline__ float sigmoidf_(float v) { return 1.0f / (1.0f + expf(-v)); }

__device__ __forceinline__ uint32_t smem_to_u32(const void* p) {
    uint32_t a;
    asm("{ .reg .u64 t; cvta.to.shared.u64 t, %1; cvt.u32.u64 %0, t; }" : "=r"(a) : "l"(p));
    return a;
}

__device__ __forceinline__ void cp16(uint32_t dst, const void* src) {
    asm volatile("cp.async.cg.shared.global [%0], [%1], 16;" :: "r"(dst), "l"(src) : "memory");
}
#define CP_COMMIT() asm volatile("cp.async.commit_group;" ::: "memory")

__device__ __forceinline__ void ldm_x4(uint32_t& r0, uint32_t& r1, uint32_t& r2, uint32_t& r3,
                                       uint32_t addr) {
    asm volatile("ldmatrix.sync.aligned.m8n8.x4.shared.b16 {%0,%1,%2,%3}, [%4];"
                 : "=r"(r0), "=r"(r1), "=r"(r2), "=r"(r3) : "r"(addr));
}

__device__ __forceinline__ void mma_fp16(float* c, const uint32_t* a, const uint32_t* b) {
    asm volatile("mma.sync.aligned.m16n8k16.row.col.f32.f16.f16.f32 "
                 "{%0,%1,%2,%3}, {%4,%5,%6,%7}, {%8,%9}, {%0,%1,%2,%3};"
                 : "+f"(c[0]), "+f"(c[1]), "+f"(c[2]), "+f"(c[3])
                 : "r"(a[0]), "r"(a[1]), "r"(a[2]), "r"(a[3]), "r"(b[0]), "r"(b[1]));
}

__device__ __forceinline__ bool flag_ok(int fs) {
    if (fs == 0) return true;
    if (fs == 4) return (g_flags[0] | g_flags[1]) != 0;
    if (fs == 5) return (g_flags[1] != 0) && (g_flags[0] == 0);
    if ((fs & 1) && g_flags[0] == 0) return false;
    if ((fs & 2) && g_flags[1] == 0) return false;
    return true;
}

// replay-safe software grid barrier (all CTAs resident: grid=296, 2 CTAs/SM)
__device__ __forceinline__ void grid_barrier(unsigned nblocks) {
    __syncthreads();
    if (threadIdx.x == 0) {
        volatile unsigned* vg = &g_bargen;
        unsigned gen = *vg;
        __threadfence();
        if (atomicAdd(&g_barcnt, 1u) == nblocks - 1u) {
            g_barcnt = 0;
            __threadfence();
            atomicAdd(&g_bargen, 1u);
        } else {
            while (*vg == gen) { }
        }
        __threadfence();
    }
    __syncthreads();
}

// ---------------- flat, byte-balanced prep (32B reads / 16B writes) ----------
__global__ void prep_flat_kernel(PrepFlat pf) {
    int z = 0;
    #pragma unroll
    for (int k = 1; k < NPREP; k++)
        if ((int)blockIdx.x >= pf.blk0[k]) z = k;
    const int lb = (int)blockIdx.x - pf.blk0[z];
    const int nb = pf.blk0[z + 1] - pf.blk0[z];
    const int n8 = pf.n4[z] >> 1;
    const float4* __restrict__ src = pf.src[z];

    if (pf.mode[z] == 1) {
        bool nz = false;
        for (int i = lb * 256 + threadIdx.x; i < n8; i += nb * 256) {
            float4 v0 = src[2 * i];
            float4 v1 = src[2 * i + 1];
            nz |= (v0.x != 0.0f) | (v0.y != 0.0f) | (v0.z != 0.0f) | (v0.w != 0.0f);
            nz |= (v1.x != 0.0f) | (v1.y != 0.0f) | (v1.z != 0.0f) | (v1.w != 0.0f);
        }
        if (nz) atomicOr(&g_flags[pf.flagidx[z]], 1);
        return;
    }
    uint4* __restrict__ dst = (uint4*)pf.dst[z];
    for (int i = lb * 256 + threadIdx.x; i < n8; i += nb * 256) {
        float4 v0 = src[2 * i];
        float4 v1 = src[2 * i + 1];
        __half2 h0 = __floats2half2_rn(v0.x, v0.y);
        __half2 h1 = __floats2half2_rn(v0.z, v0.w);
        __half2 h2 = __floats2half2_rn(v1.x, v1.y);
        __half2 h3 = __floats2half2_rn(v1.z, v1.w);
        uint4 o;
        o.x = *(uint32_t*)&h0;
        o.y = *(uint32_t*)&h1;
        o.z = *(uint32_t*)&h2;
        o.w = *(uint32_t*)&h3;
        dst[i] = o;
    }
}

// ================= shared tiling constants =================
#define BK 64
#define CHUNKS (KDIM / BK)
#define STRB 144
#define NSTAGE 3

#define CTAM 128
#define CTAN 128
#define A_BYTES (CTAM * STRB)
#define B_BYTES (CTAN * STRB)
#define STAGE_BYTES (A_BYTES + B_BYTES)
#define GEMM_SMEM (NSTAGE * STAGE_BYTES)    // 110592

// ---------------- tile core (slow path) ----------------
__device__ void gemm_tile(uint32_t sb0, int tid, int bm, int bn,
                          int npairs, const __half* const* Ap,
                          const __half* const* Wp, const int* pfs,
                          float c[4][4][4])
{
    const int lane = tid & 31;
    const int wid = tid >> 5;
    const int wm = wid & 1;
    const int wn = wid >> 1;
    const uint32_t a_row = (uint32_t)(wm * 64 + (lane & 15));
    const uint32_t a_kb  = (uint32_t)((lane >> 4) * 16);
    const uint32_t b_row = (uint32_t)(wn * 32 + (lane & 7) + ((lane & 16) ? 8 : 0));
    const uint32_t b_kb  = (uint32_t)((lane & 8) ? 16 : 0);

    for (int p = 0; p < npairs; p++) {
        if (!flag_ok(pfs[p])) continue;
        const __half* __restrict__ A = Ap[p];
        const __half* __restrict__ W = Wp[p];

        auto load_chunk = [&](int stage, int kt) {
            const uint32_t sb = sb0 + (uint32_t)stage * STAGE_BYTES;
            #pragma unroll
            for (int i = 0; i < 4; i++) {
                int gr = tid + i * 256;
                int row = gr >> 3, c8 = gr & 7;
                cp16(sb + (uint32_t)(row * STRB + c8 * 16),
                     A + (size_t)(bm + row) * KDIM + kt + c8 * 8);
            }
            #pragma unroll
            for (int i = 0; i < 4; i++) {
                int gr = tid + i * 256;
                int row = gr >> 3, c8 = gr & 7;
                cp16(sb + (uint32_t)(A_BYTES + row * STRB + c8 * 16),
                     W + (size_t)(bn + row) * KDIM + kt + c8 * 8);
            }
            CP_COMMIT();
        };

        load_chunk(0, 0);
        load_chunk(1, BK);

        int stage = 0;
        for (int ch = 0; ch < CHUNKS; ch++) {
            if (ch + 2 < CHUNKS) {
                int ns = stage + 2; if (ns >= NSTAGE) ns -= NSTAGE;
                load_chunk(ns, (ch + 2) * BK);
                asm volatile("cp.async.wait_group 2;" ::: "memory");
            } else if (ch + 1 < CHUNKS) {
                asm volatile("cp.async.wait_group 1;" ::: "memory");
            } else {
                asm volatile("cp.async.wait_group 0;" ::: "memory");
            }
            __syncthreads();

            const uint32_t As = sb0 + (uint32_t)stage * STAGE_BYTES;
            const uint32_t Bs = As + A_BYTES;

            #pragma unroll
            for (int s = 0; s < 4; s++) {
                const uint32_t kb = (uint32_t)(s * 32);
                uint32_t a[4][4];
                #pragma unroll
                for (int mf = 0; mf < 4; mf++)
                    ldm_x4(a[mf][0], a[mf][1], a[mf][2], a[mf][3],
                           As + (a_row + mf * 16) * STRB + kb + a_kb);
                uint32_t b[4][2];
                #pragma unroll
                for (int nh = 0; nh < 2; nh++) {
                    uint32_t r0, r1, r2, r3;
                    ldm_x4(r0, r1, r2, r3, Bs + (b_row + nh * 16) * STRB + kb + b_kb);
                    b[2 * nh][0] = r0;      b[2 * nh][1] = r1;
                    b[2 * nh + 1][0] = r2;  b[2 * nh + 1][1] = r3;
                }
                #pragma unroll
                for (int mf = 0; mf < 4; mf++)
                    #pragma unroll
                    for (int nf = 0; nf < 4; nf++)
                        mma_fp16(c[mf][nf], a[mf], b[nf]);
            }
            __syncthreads();
            if (++stage >= NSTAGE) stage = 0;
        }
    }
}

// ---------------- persistent slow-path mega kernel ----------------
__global__ __launch_bounds__(256, 2)
void slow_mega(SlowDesc sd)
{
    if ((g_flags[0] | g_flags[1]) == 0) return;

    extern __shared__ char smem[];
    const uint32_t sb0 = smem_to_u32(smem);
    const int tid = threadIdx.x;
    const unsigned nb = gridDim.x;

    for (int z = 0; z < 9; z++) {
        if (!flag_ok(sd.cfs[z])) continue;
        const float4* __restrict__ src = sd.csrc[z];
        uint2* __restrict__ dst = sd.cdst[z];
        const int n4 = sd.cn4[z];
        for (int i = blockIdx.x * 256 + tid; i < n4; i += nb * 256) {
            float4 v = src[i];
            __half2 h0 = __floats2half2_rn(v.x, v.y);
            __half2 h1 = __floats2half2_rn(v.z, v.w);
            uint2 o;
            o.x = *(uint32_t*)&h0;
            o.y = *(uint32_t*)&h1;
            dst[i] = o;
        }
    }
    grid_barrier(nb);

    const int lane = tid & 31;
    const int wid = tid >> 5;
    const int g = lane >> 2;
    const int t = lane & 3;
    const int wm = wid & 1;
    const int wn = wid >> 1;

    for (int ti = blockIdx.x; ti < 3 * 512; ti += (int)nb) {
        const int z = ti >> 9;
        const int tt = ti & 511;
        if (!flag_ok(sd.sfs2[z])) continue;
        const int bn = (tt & 15) * CTAN;
        const int bm = (tt >> 4) * CTAM;

        float c[4][4][4];
        #pragma unroll
        for (int i = 0; i < 4; i++)
            #pragma unroll
            for (int j = 0; j < 4; j++)
                #pragma unroll
                for (int q = 0; q < 4; q++) c[i][j][q] = 0.0f;

        gemm_tile(sb0, tid, bm, bn, sd.np2[z], sd.A2[z], sd.W2[z], sd.pfs2[z], c);

        if (sd.epi2[z] == 2) {
            const float* __restrict__ m0p = sd.mem0;
            __half* __restrict__ aup = sd.aup;
            const float* b0 = sd.bb0[z];
            const float* b1 = sd.bb1[z];
            const float* b2 = sd.bb2[z];
            #pragma unroll
            for (int nf = 0; nf < 4; nf++) {
                const int col = bn + wn * 32 + nf * 8 + 2 * t;
                float bs0 = b0[col] + b1[col] + b2[col];
                float bs1 = b0[col + 1] + b1[col + 1] + b2[col + 1];
                #pragma unroll
                for (int mf = 0; mf < 4; mf++) {
                    const int r = bm + wm * 64 + mf * 16 + g;
                    float2 v0 = make_float2(c[mf][nf][0] + bs0, c[mf][nf][1] + bs1);
                    float2 v1 = make_float2(c[mf][nf][2] + bs0, c[mf][nf][3] + bs1);
                    float2 m0 = *(const float2*)(m0p + (size_t)r * DDIM + col);
                    float2 m1 = *(const float2*)(m0p + (size_t)(r + 8) * DDIM + col);
                    __half2 h0 = __floats2half2_rn(sigmoidf_(v0.x) * m0.x,
                                                   sigmoidf_(v0.y) * m0.y);
                    __half2 h1 = __floats2half2_rn(sigmoidf_(v1.x) * m1.x,
                                                   sigmoidf_(v1.y) * m1.y);
                    *(__half2*)(aup + (size_t)r * KDIM + col) = h0;
                    *(__half2*)(aup + (size_t)(r + 8) * KDIM + col) = h1;
                }
            }
        } else {
            float* __restrict__ C = sd.C2[z];
            #pragma unroll
            for (int nf = 0; nf < 4; nf++) {
                const int col = bn + wn * 32 + nf * 8 + 2 * t;
                #pragma unroll
                for (int mf = 0; mf < 4; mf++) {
                    const int r = bm + wm * 64 + mf * 16 + g;
                    float2* p0 = (float2*)(C + (size_t)r * DDIM + col);
                    float2* p1 = (float2*)(C + (size_t)(r + 8) * DDIM + col);
                    float2 o0 = *p0, o1 = *p1;
                    o0.x += c[mf][nf][0]; o0.y += c[mf][nf][1];
                    o1.x += c[mf][nf][2]; o1.y += c[mf][nf][3];
                    *p0 = o0;
                    *p1 = o1;
                }
            }
        }
    }
    grid_barrier(nb);

    for (int ti = blockIdx.x; ti < 2 * 512; ti += (int)nb) {
        const int z = ti >> 9;
        const int tt = ti & 511;
        const int bn = (tt & 15) * CTAN;
        const int bm = (tt >> 4) * CTAM;

        if (z == 0) {
            if (g_flags[0] == 0) continue;
            float c[4][4][4];
            #pragma unroll
            for (int i = 0; i < 4; i++)
                #pragma unroll
                for (int j = 0; j < 4; j++)
                    #pragma unroll
                    for (int q = 0; q < 4; q++) c[i][j][q] = 0.0f;
            const __half* Ap[1] = { sd.Adec };
            const __half* Wp[1] = { sd.Wdec };
            const int pf[1] = { 0 };
            gemm_tile(sb0, tid, bm, bn, 1, Ap, Wp, pf, c);

            #pragma unroll
            for (int nf = 0; nf < 4; nf++) {
                const int col = bn + wn * 32 + nf * 8 + 2 * t;
                const float d0 = sd.bdec[col], d1 = sd.bdec[col + 1];
                #pragma unroll
                for (int mf = 0; mf < 4; mf++) {
                    const int r = bm + wm * 64 + mf * 16 + g;
                    float2 pa0 = *(const float2*)(sd.preA_in + (size_t)r * DDIM + col);
                    float2 pa1 = *(const float2*)(sd.preA_in + (size_t)(r + 8) * DDIM + col);
                    float2 pb0 = *(const float2*)(sd.preB_in + (size_t)r * DDIM + col);
                    float2 pb1 = *(const float2*)(sd.preB_in + (size_t)(r + 8) * DDIM + col);
                    float2 o0, o1;
                    o0.x = c[mf][nf][0] + d0 + sigmoidf_(pa0.x) * sigmoidf_(pb0.x);
                    o0.y = c[mf][nf][1] + d1 + sigmoidf_(pa0.y) * sigmoidf_(pb0.y);
                    o1.x = c[mf][nf][2] + d0 + sigmoidf_(pa1.x) * sigmoidf_(pb1.x);
                    o1.y = c[mf][nf][3] + d1 + sigmoidf_(pa1.y) * sigmoidf_(pb1.y);
                    *(float2*)(sd.outp + (size_t)r * DDIM + col) = o0;
                    *(float2*)(sd.outp + (size_t)(r + 8) * DDIM + col) = o1;
                }
            }
        } else {
            if (!(g_flags[1] != 0 && g_flags[0] == 0)) continue;
            #pragma unroll
            for (int nf = 0; nf < 4; nf++) {
                const int col = bn + wn * 32 + nf * 8 + 2 * t;
                const float d0 = sd.bdec[col], d1 = sd.bdec[col + 1];
                #pragma unroll
                for (int mf = 0; mf < 4; mf++) {
                    const int r = bm + wm * 64 + mf * 16 + g;
                    float2 pa0 = *(const float2*)(sd.preA_in + (size_t)r * DDIM + col);
                    float2 pa1 = *(const float2*)(sd.preA_in + (size_t)(r + 8) * DDIM + col);
                    float2 pb0 = *(const float2*)(sd.preB_in + (size_t)r * DDIM + col);
                    float2 pb1 = *(const float2*)(sd.preB_in + (size_t)(r + 8) * DDIM + col);
                    float2 o0, o1;
                    o0.x = d0 + sigmoidf_(pa0.x) * sigmoidf_(pb0.x);
                    o0.y = d1 + sigmoidf_(pa0.y) * sigmoidf_(pb0.y);
                    o1.x = d0 + sigmoidf_(pa1.x) * sigmoidf_(pb1.x);
                    o1.y = d1 + sigmoidf_(pa1.y) * sigmoidf_(pb1.y);
                    *(float2*)(sd.outp + (size_t)r * DDIM + col) = o0;
                    *(float2*)(sd.outp + (size_t)(r + 8) * DDIM + col) = o1;
                }
            }
        }
    }
}

// ---------------- dual-output GEMM (fast path) — proven 128x64 tiles ----
#define DCTAM 128
#define DCTAN 64
#define D_A_BYTES (DCTAM * STRB)                 // 18432
#define D_W_BYTES (DCTAN * STRB)                 // 9216
#define D_STAGE (D_A_BYTES + 2 * D_W_BYTES)      // 36864
#define DGEMM_SMEM (NSTAGE * D_STAGE)            // 110592

__global__ __launch_bounds__(256, 2)
void gemm_dual(const __half* __restrict__ A,
               const __half* __restrict__ W0, const __half* __restrict__ W1,
               float* __restrict__ preA, float* __restrict__ preB,
               const float* __restrict__ bA0, const float* __restrict__ bA1,
               const float* __restrict__ bB0, const float* __restrict__ bB1,
               const float* __restrict__ bB2,
               float* __restrict__ outp, const float* __restrict__ bdec)
{
    extern __shared__ char smem[];
    const uint32_t sb0 = smem_to_u32(smem);

    const int tid = threadIdx.x;
    const int wid = tid >> 5;
    const int lane = tid & 31;
    const int g = lane >> 2;
    const int t = lane & 3;
    const int wm = wid & 1;
    const int wn = wid >> 1;
    const int bm = blockIdx.y * DCTAM;
    const int bn = blockIdx.x * DCTAN;

    float cA[4][2][4], cB[4][2][4];
    #pragma unroll
    for (int i = 0; i < 4; i++)
        #pragma unroll
        for (int j = 0; j < 2; j++)
            #pragma unroll
            for (int q = 0; q < 4; q++) { cA[i][j][q] = 0.0f; cB[i][j][q] = 0.0f; }

    const uint32_t a_row = (uint32_t)(wm * 64 + (lane & 15));
    const uint32_t a_kb  = (uint32_t)((lane >> 4) * 16);
    const uint32_t b_row = (uint32_t)(wn * 16 + (lane & 7) + ((lane & 16) ? 8 : 0));
    const uint32_t b_kb  = (uint32_t)((lane & 8) ? 16 : 0);

    auto load_chunk = [&](int stage, int kt) {
        const uint32_t sb = sb0 + (uint32_t)stage * D_STAGE;
        #pragma unroll
        for (int i = 0; i < 4; i++) {
            int gr = tid + i * 256;
            int row = gr >> 3, c8 = gr & 7;
            cp16(sb + (uint32_t)(row * STRB + c8 * 16),
                 A + (size_t)(bm + row) * KDIM + kt + c8 * 8);
        }
        #pragma unroll
        for (int i = 0; i < 2; i++) {
            int gr = tid + i * 256;
            int row = gr >> 3, c8 = gr & 7;
            cp16(sb + (uint32_t)(D_A_BYTES + row * STRB + c8 * 16),
                 W0 + (size_t)(bn + row) * KDIM + kt + c8 * 8);
        }
        #pragma unroll
        for (int i = 0; i < 2; i++) {
            int gr = tid + i * 256;
            int row = gr >> 3, c8 = gr & 7;
            cp16(sb + (uint32_t)(D_A_BYTES + D_W_BYTES + row * STRB + c8 * 16),
                 W1 + (size_t)(bn + row) * KDIM + kt + c8 * 8);
        }
        CP_COMMIT();
    };

    load_chunk(0, 0);
    load_chunk(1, BK);

    int stage = 0;
    for (int ch = 0; ch < CHUNKS; ch++) {
        if (ch + 2 < CHUNKS) {
            int ns = stage + 2; if (ns >= NSTAGE) ns -= NSTAGE;
            load_chunk(ns, (ch + 2) * BK);
            asm volatile("cp.async.wait_group 2;" ::: "memory");
        } else if (ch + 1 < CHUNKS) {
            asm volatile("cp.async.wait_group 1;" ::: "memory");
        } else {
            asm volatile("cp.async.wait_group 0;" ::: "memory");
        }
        __syncthreads();

        const uint32_t As  = sb0 + (uint32_t)stage * D_STAGE;
        const uint32_t Bs0 = As + D_A_BYTES;
        const uint32_t Bs1 = Bs0 + D_W_BYTES;

        #pragma unroll
        for (int s = 0; s < 4; s++) {
            const uint32_t kb = (uint32_t)(s * 32);
            uint32_t a[4][4];
            #pragma unroll
            for (int mf = 0; mf < 4; mf++)
                ldm_x4(a[mf][0], a[mf][1], a[mf][2], a[mf][3],
                       As + (a_row + mf * 16) * STRB + kb + a_kb);
            uint32_t b0[2][2], b1[2][2];
            {
                uint32_t r0, r1, r2, r3;
                ldm_x4(r0, r1, r2, r3, Bs0 + b_row * STRB + kb + b_kb);
                b0[0][0] = r0; b0[0][1] = r1; b0[1][0] = r2; b0[1][1] = r3;
                ldm_x4(r0, r1, r2, r3, Bs1 + b_row * STRB + kb + b_kb);
                b1[0][0] = r0; b1[0][1] = r1; b1[1][0] = r2; b1[1][1] = r3;
            }
            #pragma unroll
            for (int mf = 0; mf < 4; mf++)
                #pragma unroll
                for (int nf = 0; nf < 2; nf++) {
                    mma_fp16(cA[mf][nf], a[mf], b0[nf]);
                    mma_fp16(cB[mf][nf], a[mf], b1[nf]);
                }
        }
        __syncthreads();
        if (++stage >= NSTAGE) stage = 0;
    }

    // ---- fused epilogue ----
    const bool slow = (g_flags[0] | g_flags[1]) != 0;
    #pragma unroll
    for (int nf = 0; nf < 2; nf++) {
        const int col = bn + wn * 16 + nf * 8 + 2 * t;
        const float bsA0 = bA0[col] + bA1[col];
        const float bsA1 = bA0[col + 1] + bA1[col + 1];
        const float bsB0 = bB0[col] + bB1[col] + bB2[col];
        const float bsB1 = bB0[col + 1] + bB1[col + 1] + bB2[col + 1];
        const float d0 = bdec[col], d1 = bdec[col + 1];
        #pragma unroll
        for (int mf = 0; mf < 4; mf++) {
            const int r = bm + wm * 64 + mf * 16 + g;
            float2 va0 = make_float2(cA[mf][nf][0] + bsA0, cA[mf][nf][1] + bsA1);
            float2 va1 = make_float2(cA[mf][nf][2] + bsA0, cA[mf][nf][3] + bsA1);
            float2 vb0 = make_float2(cB[mf][nf][0] + bsB0, cB[mf][nf][1] + bsB1);
            float2 vb1 = make_float2(cB[mf][nf][2] + bsB0, cB[mf][nf][3] + bsB1);
            if (slow) {
                *(float2*)(preA + (size_t)r * DDIM + col) = va0;
                *(float2*)(preA + (size_t)(r + 8) * DDIM + col) = va1;
                *(float2*)(preB + (size_t)r * DDIM + col) = vb0;
                *(float2*)(preB + (size_t)(r + 8) * DDIM + col) = vb1;
            } else {
                float2 o0, o1;
                o0.x = d0 + sigmoidf_(va0.x) * sigmoidf_(vb0.x);
                o0.y = d1 + sigmoidf_(va0.y) * sigmoidf_(vb0.y);
                o1.x = d0 + sigmoidf_(va1.x) * sigmoidf_(vb1.x);
                o1.y = d1 + sigmoidf_(va1.y) * sigmoidf_(vb1.y);
                *(float2*)(outp + (size_t)r * DDIM + col) = o0;
                *(float2*)(outp + (size_t)(r + 8) * DDIM + col) = o1;
            }
        }
    }
}

// ---------------- host orchestration ----------------
extern "C" void kernel_launch(void* const* d_in, const int* in_sizes, int n_in,
                              void* d_out, int out_size) {
    const float* x              = (const float*)d_in[0];
    const float* out0           = (const float*)d_in[1];
    const float* mem0           = (const float*)d_in[2];
    const float* w_inpgate      = (const float*)d_in[3];
    const float* b_inpgate      = (const float*)d_in[4];
    const float* w_rec_inpgate  = (const float*)d_in[5];
    const float* b_rec_inpgate  = (const float*)d_in[6];
    const float* w_mem_inpgate  = (const float*)d_in[7];
    const float* b_mem_inpgate  = (const float*)d_in[8];
    const float* w_inp          = (const float*)d_in[9];
    const float* b_inp          = (const float*)d_in[10];
    const float* w_rec_inp      = (const float*)d_in[11];
    const float* b_rec_inp      = (const float*)d_in[12];
    const float* w_readgate     = (const float*)d_in[13];
    const float* b_readgate     = (const float*)d_in[14];
    const float* w_rec_readgate = (const float*)d_in[15];
    const float* b_rec_readgate = (const float*)d_in[16];
    const float* w_mem_readgate = (const float*)d_in[17];
    const float* b_mem_readgate = (const float*)d_in[18];
    const float* w_decoder      = (const float*)d_in[19];
    const float* b_decoder      = (const float*)d_in[20];
    float* out = (float*)d_out;

    void *pA, *pB, *pax, *pay, *paz, *pau;
    void *pw0, *pw1, *pw2, *pw3, *pw4, *pw5, *pw6;
    cudaGetSymbolAddress(&pA, g_preA); cudaGetSymbolAddress(&pB, g_preB);
    cudaGetSymbolAddress(&pax, g_ax);  cudaGetSymbolAddress(&pay, g_ay);
    cudaGetSymbolAddress(&paz, g_az);  cudaGetSymbolAddress(&pau, g_au);
    cudaGetSymbolAddress(&pw0, g_w0);  cudaGetSymbolAddress(&pw1, g_w1);
    cudaGetSymbolAddress(&pw2, g_w2);  cudaGetSymbolAddress(&pw3, g_w3);
    cudaGetSymbolAddress(&pw4, g_w4);  cudaGetSymbolAddress(&pw5, g_w5);
    cudaGetSymbolAddress(&pw6, g_w6);
    float* preA = (float*)pA;  float* preB = (float*)pB;
    __half* ax = (__half*)pax; __half* ay = (__half*)pay;
    __half* az = (__half*)paz; __half* au = (__half*)pau;
    __half* w0h = (__half*)pw0; __half* w1h = (__half*)pw1; __half* w2h = (__half*)pw2;
    __half* w3h = (__half*)pw3; __half* w4h = (__half*)pw4; __half* w5h = (__half*)pw5;
    __half* w6h = (__half*)pw6;

    cudaFuncSetAttribute(slow_mega, cudaFuncAttributeMaxDynamicSharedMemorySize, GEMM_SMEM);
    cudaFuncSetAttribute(gemm_dual, cudaFuncAttributeMaxDynamicSharedMemorySize, DGEMM_SMEM);

    const int nA4 = (BDIM * KDIM) / 4;
    const int nW4 = (DDIM * KDIM) / 4;
    const dim3 DGRID(DDIM / DCTAN, BDIM / DCTAM, 1);  // 32 x 32 = 1024

    // L1: flat, byte-balanced ungated prep
    {
        PrepFlat pf = {};
        pf.src[0] = (const float4*)x;         pf.dst[0] = (uint2*)ax;  pf.n4[0] = nA4; pf.mode[0] = 0;
        pf.src[1] = (const float4*)mem0;      pf.n4[1] = nA4; pf.mode[1] = 1; pf.flagidx[1] = 0;
        pf.src[2] = (const float4*)out0;      pf.n4[2] = nA4; pf.mode[2] = 1; pf.flagidx[2] = 1;
        pf.src[3] = (const float4*)w_inp;     pf.dst[3] = (uint2*)w0h; pf.n4[3] = nW4; pf.mode[3] = 0;
        pf.src[4] = (const float4*)w_inpgate; pf.dst[4] = (uint2*)w1h; pf.n4[4] = nW4; pf.mode[4] = 0;
        pf.blk0[0] = 0;
        pf.blk0[1] = 615;
        pf.blk0[2] = 1025;
        pf.blk0[3] = 1435;
        pf.blk0[4] = 1742;
        pf.blk0[5] = 2048;
        prep_flat_kernel<<<2048, 256>>>(pf);
    }

    // L2: dual GEMM (proven 1024-tile full-K version)
    gemm_dual<<<DGRID, 256, DGEMM_SMEM>>>(ax, w0h, w1h, preA, preB,
                                          b_inp, b_rec_inp,
                                          b_inpgate, b_mem_inpgate, b_rec_inpgate,
                                          out, b_decoder);

    // L3: persistent slow-path mega kernel (single gated launch)
    {
        SlowDesc sd = {};
        sd.csrc[0] = (const float4*)out0;            sd.cdst[0] = (uint2*)ay;  sd.cn4[0] = nA4; sd.cfs[0] = 2;
        sd.csrc[1] = (const float4*)mem0;            sd.cdst[1] = (uint2*)az;  sd.cn4[1] = nA4; sd.cfs[1] = 1;
        sd.csrc[2] = (const float4*)w_readgate;      sd.cdst[2] = (uint2*)w2h; sd.cn4[2] = nW4; sd.cfs[2] = 1;
        sd.csrc[3] = (const float4*)w_rec_inp;       sd.cdst[3] = (uint2*)w3h; sd.cn4[3] = nW4; sd.cfs[3] = 2;
        sd.csrc[4] = (const float4*)w_rec_inpgate;   sd.cdst[4] = (uint2*)w4h; sd.cn4[4] = nW4; sd.cfs[4] = 2;
        sd.csrc[5] = (const float4*)w_rec_readgate;  sd.cdst[5] = (uint2*)w5h; sd.cn4[5] = nW4; sd.cfs[5] = 3;
        sd.csrc[6] = (const float4*)w_mem_inpgate;   sd.cdst[6] = (uint2*)w0h; sd.cn4[6] = nW4; sd.cfs[6] = 1;
        sd.csrc[7] = (const float4*)w_mem_readgate;  sd.cdst[7] = (uint2*)w1h; sd.cn4[7] = nW4; sd.cfs[7] = 1;
        sd.csrc[8] = (const float4*)w_decoder;       sd.cdst[8] = (uint2*)w6h; sd.cn4[8] = nW4; sd.cfs[8] = 1;
        sd.sfs2[0] = 1; sd.np2[0] = 3; sd.epi2[0] = 2;
        sd.A2[0][0] = ax; sd.W2[0][0] = w2h; sd.pfs2[0][0] = 1;
        sd.A2[0][1] = ay; sd.W2[0][1] = w5h; sd.pfs2[0][1] = 3;
        sd.A2[0][2] = az; sd.W2[0][2] = w1h; sd.pfs2[0][2] = 1;
        sd.bb0[0] = b_readgate; sd.bb1[0] = b_mem_readgate; sd.bb2[0] = b_rec_readgate;
        sd.sfs2[1] = 2; sd.np2[1] = 1; sd.epi2[1] = 0;
        sd.A2[1][0] = ay; sd.W2[1][0] = w3h; sd.pfs2[1][0] = 2;
        sd.C2[1] = preA;
        sd.sfs2[2] = 4; sd.np2[2] = 2; sd.epi2[2] = 0;
        sd.A2[2][0] = ay; sd.W2[2][0] = w4h; sd.pfs2[2][0] = 2;
        sd.A2[2][1] = az; sd.W2[2][1] = w0h; sd.pfs2[2][1] = 1;
        sd.C2[2] = preB;
        sd.Adec = au; sd.Wdec = w6h;
        sd.bdec = b_decoder;
        sd.preA_in = preA; sd.preB_in = preB; sd.outp = out;
        sd.mem0 = mem0; sd.aup = au;
        slow_mega<<<296, 256, GEMM_SMEM>>>(sd);
    }
}